// round 15
// baseline (speedup 1.0000x reference)
#include <cuda_runtime.h>
#include <cstdint>

#define F_DIM 64
#define F_VEC2 32           // 64 floats = 32 float2; lane l owns float2 #l
#define MAX_NODES 100000
#define CAP 64              // bucket capacity per node (deg ~ Poisson(8))
#define CAP_SHIFT 6

// Scratch (no allocation allowed). Zero-initialized. Bucket slots beyond a
// node's degree are never written (degrees identical every launch), so
// speculative gathers through them read row 0 (valid memory, add masked).
// g_cursor is returned to all-zero by k_seg at the end of every launch.
__device__ int g_cursor[MAX_NODES];           // per-node fill cursor == degree
__device__ int g_bucket[MAX_NODES * CAP];     // src ids bucketed by tgt (25.6MB)

// ---------------------------------------------------------------------------
// K1: bucket scatter of src ids by tgt. 8 edges/thread via two int4 pairs.
// start[t] implicit (t*CAP): no count pass, no prefix scan.
// Requires cursor == 0 on entry (initial zero-init + k_seg self-clearing).
// ---------------------------------------------------------------------------
__global__ void k_sortsrc(const int4* __restrict__ src4,
                          const int4* __restrict__ tgt4,
                          int* __restrict__ cursor,
                          int* __restrict__ bucket,
                          int n_groups) {
    int g = (blockIdx.x * blockDim.x + threadIdx.x) * 2;
    if (g >= n_groups) return;

    int4 s0 = src4[g];
    int4 t0 = tgt4[g];
    bool two = (g + 1) < n_groups;
    int4 s1 = two ? src4[g + 1] : make_int4(0, 0, 0, 0);
    int4 t1 = two ? tgt4[g + 1] : make_int4(0, 0, 0, 0);

    int p0 = atomicAdd(&cursor[t0.x], 1);
    int p1 = atomicAdd(&cursor[t0.y], 1);
    int p2 = atomicAdd(&cursor[t0.z], 1);
    int p3 = atomicAdd(&cursor[t0.w], 1);
    int p4 = two ? atomicAdd(&cursor[t1.x], 1) : 0;
    int p5 = two ? atomicAdd(&cursor[t1.y], 1) : 0;
    int p6 = two ? atomicAdd(&cursor[t1.z], 1) : 0;
    int p7 = two ? atomicAdd(&cursor[t1.w], 1) : 0;

    bucket[(t0.x << CAP_SHIFT) + p0] = s0.x;
    bucket[(t0.y << CAP_SHIFT) + p1] = s0.y;
    bucket[(t0.z << CAP_SHIFT) + p2] = s0.z;
    bucket[(t0.w << CAP_SHIFT) + p3] = s0.w;
    if (two) {
        bucket[(t1.x << CAP_SHIFT) + p4] = s1.x;
        bucket[(t1.y << CAP_SHIFT) + p5] = s1.y;
        bucket[(t1.z << CAP_SHIFT) + p6] = s1.z;
        bucket[(t1.w << CAP_SHIFT) + p7] = s1.w;
    }
}

// ---------------------------------------------------------------------------
// K2: segmented mean. ONE NODE PER WARP, float2 lanes, 2-hop for deg<=16.
// hop 1: cursor + ALL FOUR index int4s (16 indices) issue together.
// hop 2: first 8 gathers speculative (adds masked; unused slots read row 0),
//        gathers 8..15 predicated per-slot (no extra traffic) — indices are
//        already resident, so deg<=16 nodes (99.6%) need no further hop.
// Tail loop only for deg > 16 (~0.4% of nodes), warp-uniform.
// Lane 0 clears cursor[node] at the end (replaces the memset pass).
// ---------------------------------------------------------------------------
__global__ void __launch_bounds__(256) k_seg(
        const float2* __restrict__ x2,
        const int* __restrict__ bucket,
        int* __restrict__ cursor,
        float2* __restrict__ out2,
        int n_nodes) {
    int node = (blockIdx.x * blockDim.x + threadIdx.x) >> 5;
    int lane = threadIdx.x & 31;
    if (node >= n_nodes) return;

    const int4* seg = (const int4*)(bucket + ((size_t)node << CAP_SHIFT));

    // hop 1: all independent (CAP=64 -> seg[0..3] always in-bounds)
    int  c  = __ldg(&cursor[node]);
    int4 i0 = __ldg(&seg[0]);
    int4 i1 = __ldg(&seg[1]);
    int4 i2 = __ldg(&seg[2]);
    int4 i3 = __ldg(&seg[3]);

    // hop 2a: 8 speculative gathers, adds masked
    float2 a0 = __ldg(&x2[i0.x * F_VEC2 + lane]);
    float2 a1 = __ldg(&x2[i0.y * F_VEC2 + lane]);
    float2 a2 = __ldg(&x2[i0.z * F_VEC2 + lane]);
    float2 a3 = __ldg(&x2[i0.w * F_VEC2 + lane]);
    float2 a4 = __ldg(&x2[i1.x * F_VEC2 + lane]);
    float2 a5 = __ldg(&x2[i1.y * F_VEC2 + lane]);
    float2 a6 = __ldg(&x2[i1.z * F_VEC2 + lane]);
    float2 a7 = __ldg(&x2[i1.w * F_VEC2 + lane]);

    float2 acc = make_float2(0.f, 0.f);
    if (c > 0) { acc.x += a0.x; acc.y += a0.y; }
    if (c > 1) { acc.x += a1.x; acc.y += a1.y; }
    if (c > 2) { acc.x += a2.x; acc.y += a2.y; }
    if (c > 3) { acc.x += a3.x; acc.y += a3.y; }
    if (c > 4) { acc.x += a4.x; acc.y += a4.y; }
    if (c > 5) { acc.x += a5.x; acc.y += a5.y; }
    if (c > 6) { acc.x += a6.x; acc.y += a6.y; }
    if (c > 7) { acc.x += a7.x; acc.y += a7.y; }

    // hop 2b: gathers 8..15 predicated per-slot (indices already resident,
    // zero traffic when deg <= 8, no additional latency hop for deg 9..16)
    if (c > 8) {
        if (c > 8)  { float2 a = __ldg(&x2[i2.x * F_VEC2 + lane]);
                      acc.x += a.x; acc.y += a.y; }
        if (c > 9)  { float2 a = __ldg(&x2[i2.y * F_VEC2 + lane]);
                      acc.x += a.x; acc.y += a.y; }
        if (c > 10) { float2 a = __ldg(&x2[i2.z * F_VEC2 + lane]);
                      acc.x += a.x; acc.y += a.y; }
        if (c > 11) { float2 a = __ldg(&x2[i2.w * F_VEC2 + lane]);
                      acc.x += a.x; acc.y += a.y; }
        if (c > 12) { float2 a = __ldg(&x2[i3.x * F_VEC2 + lane]);
                      acc.x += a.x; acc.y += a.y; }
        if (c > 13) { float2 a = __ldg(&x2[i3.y * F_VEC2 + lane]);
                      acc.x += a.x; acc.y += a.y; }
        if (c > 14) { float2 a = __ldg(&x2[i3.z * F_VEC2 + lane]);
                      acc.x += a.x; acc.y += a.y; }
        if (c > 15) { float2 a = __ldg(&x2[i3.w * F_VEC2 + lane]);
                      acc.x += a.x; acc.y += a.y; }

        // deg > 16: rare (~0.4% of nodes), warp-uniform
        for (int base = 16; base < c; base += 4) {
            int4 j = __ldg(&seg[base >> 2]);
            if (base + 0 < c) { float2 a = __ldg(&x2[j.x * F_VEC2 + lane]);
                                acc.x += a.x; acc.y += a.y; }
            if (base + 1 < c) { float2 a = __ldg(&x2[j.y * F_VEC2 + lane]);
                                acc.x += a.x; acc.y += a.y; }
            if (base + 2 < c) { float2 a = __ldg(&x2[j.z * F_VEC2 + lane]);
                                acc.x += a.x; acc.y += a.y; }
            if (base + 3 < c) { float2 a = __ldg(&x2[j.w * F_VEC2 + lane]);
                                acc.x += a.x; acc.y += a.y; }
        }
    }

    float w = 1.0f / (float)(c > 0 ? c : 1);
    acc.x *= w; acc.y *= w;
    out2[node * F_VEC2 + lane] = acc;

    // restore cursor to 0 for the next launch (replaces the memset pass)
    if (lane == 0) cursor[node] = 0;
}

// ---------------------------------------------------------------------------
// Launch
// ---------------------------------------------------------------------------
extern "C" void kernel_launch(void* const* d_in, const int* in_sizes, int n_in,
                              void* d_out, int out_size) {
    const float* x   = (const float*)d_in[0];
    const int*   src = (const int*)d_in[1];
    const int*   tgt = (const int*)d_in[2];
    float*       out = (float*)d_out;

    int n_nodes  = in_sizes[0] / F_DIM;   // 100000
    int n_edges  = in_sizes[1];           // 800000
    int n_groups = n_edges / 4;

    int *cursor, *bucket;
    cudaGetSymbolAddress((void**)&cursor, g_cursor);
    cudaGetSymbolAddress((void**)&bucket, g_bucket);

    const int B = 256;

    // no memset: cursor is zero on first launch (static init) and k_seg
    // returns it to zero at the end of every launch.
    {
        int threads_needed = (n_groups + 1) / 2;
        k_sortsrc<<<(threads_needed + B - 1) / B, B>>>(
            (const int4*)src, (const int4*)tgt, cursor, bucket, n_groups);
    }
    {
        // one warp per node
        long long threads = (long long)n_nodes * 32;
        int grid = (int)((threads + B - 1) / B);
        k_seg<<<grid, B>>>((const float2*)x, bucket, cursor,
                           (float2*)out, n_nodes);
    }
}

// round 16
// speedup vs baseline: 1.0304x; 1.0304x over previous
#include <cuda_runtime.h>
#include <cstdint>

#define F_DIM 64
#define F_VEC2 32           // 64 floats = 32 float2; lane l owns float2 #l
#define MAX_NODES 100000
#define CAP 64              // bucket capacity per node (deg ~ Poisson(8))
#define CAP_SHIFT 6

// Scratch (no allocation allowed). Zero-initialized. Bucket slots beyond a
// node's degree are never written (degrees identical every launch), so
// speculative gathers through them read row 0 (valid memory, add masked).
// g_cursor is returned to all-zero by k_seg at the end of every launch.
__device__ int g_cursor[MAX_NODES];           // per-node fill cursor == degree
__device__ int g_bucket[MAX_NODES * CAP];     // src ids bucketed by tgt (25.6MB)

// ---------------------------------------------------------------------------
// K1: bucket scatter of src ids by tgt. 4 edges/thread via int4 loads
// (empirically faster than 8/thread: denser atomic issue, no predication).
// start[t] implicit (t*CAP): no count pass, no prefix scan.
// Requires cursor == 0 on entry (initial zero-init + k_seg self-clearing).
// ---------------------------------------------------------------------------
__global__ void k_sortsrc(const int4* __restrict__ src4,
                          const int4* __restrict__ tgt4,
                          int* __restrict__ cursor,
                          int* __restrict__ bucket,
                          int n_groups) {
    int g = blockIdx.x * blockDim.x + threadIdx.x;
    if (g < n_groups) {
        int4 s = src4[g];
        int4 t = tgt4[g];
        int p0 = atomicAdd(&cursor[t.x], 1);
        int p1 = atomicAdd(&cursor[t.y], 1);
        int p2 = atomicAdd(&cursor[t.z], 1);
        int p3 = atomicAdd(&cursor[t.w], 1);
        bucket[(t.x << CAP_SHIFT) + p0] = s.x;
        bucket[(t.y << CAP_SHIFT) + p1] = s.y;
        bucket[(t.z << CAP_SHIFT) + p2] = s.z;
        bucket[(t.w << CAP_SHIFT) + p3] = s.w;
    }
}

// ---------------------------------------------------------------------------
// K2: segmented mean (round-14 structure — empirically best).
// ONE NODE PER WARP, float2 lanes, speculative gathers.
// hop 1: cursor + first two index int4s issue together (independent).
// hop 2: 8 unconditional LDG.64 gathers (adds predicated on degree).
// Tail loop only for deg > 8 (~40% of nodes), warp-uniform.
// Lane 0 clears cursor[node] at the end (replaces the memset pass).
// ---------------------------------------------------------------------------
__global__ void __launch_bounds__(256) k_seg(
        const float2* __restrict__ x2,
        const int* __restrict__ bucket,
        int* __restrict__ cursor,
        float2* __restrict__ out2,
        int n_nodes) {
    int node = (blockIdx.x * blockDim.x + threadIdx.x) >> 5;
    int lane = threadIdx.x & 31;
    if (node >= n_nodes) return;

    const int4* seg = (const int4*)(bucket + ((size_t)node << CAP_SHIFT));

    // hop 1: all independent
    int  c  = __ldg(&cursor[node]);
    int4 i0 = __ldg(&seg[0]);
    int4 i1 = __ldg(&seg[1]);

    // hop 2: 8 speculative gathers (row 0 for unused slots), adds masked
    float2 a0 = __ldg(&x2[i0.x * F_VEC2 + lane]);
    float2 a1 = __ldg(&x2[i0.y * F_VEC2 + lane]);
    float2 a2 = __ldg(&x2[i0.z * F_VEC2 + lane]);
    float2 a3 = __ldg(&x2[i0.w * F_VEC2 + lane]);
    float2 a4 = __ldg(&x2[i1.x * F_VEC2 + lane]);
    float2 a5 = __ldg(&x2[i1.y * F_VEC2 + lane]);
    float2 a6 = __ldg(&x2[i1.z * F_VEC2 + lane]);
    float2 a7 = __ldg(&x2[i1.w * F_VEC2 + lane]);

    float2 acc = make_float2(0.f, 0.f);
    if (c > 0) { acc.x += a0.x; acc.y += a0.y; }
    if (c > 1) { acc.x += a1.x; acc.y += a1.y; }
    if (c > 2) { acc.x += a2.x; acc.y += a2.y; }
    if (c > 3) { acc.x += a3.x; acc.y += a3.y; }
    if (c > 4) { acc.x += a4.x; acc.y += a4.y; }
    if (c > 5) { acc.x += a5.x; acc.y += a5.y; }
    if (c > 6) { acc.x += a6.x; acc.y += a6.y; }
    if (c > 7) { acc.x += a7.x; acc.y += a7.y; }

    // warp-uniform tail for deg > 8
    for (int base = 8; base < c; base += 8) {
        int q = base >> 2;
        int4 j0 = __ldg(&seg[q]);
        int4 j1 = __ldg(&seg[q + 1]);
        if (base + 0 < c) { float2 a = __ldg(&x2[j0.x * F_VEC2 + lane]);
                            acc.x += a.x; acc.y += a.y; }
        if (base + 1 < c) { float2 a = __ldg(&x2[j0.y * F_VEC2 + lane]);
                            acc.x += a.x; acc.y += a.y; }
        if (base + 2 < c) { float2 a = __ldg(&x2[j0.z * F_VEC2 + lane]);
                            acc.x += a.x; acc.y += a.y; }
        if (base + 3 < c) { float2 a = __ldg(&x2[j0.w * F_VEC2 + lane]);
                            acc.x += a.x; acc.y += a.y; }
        if (base + 4 < c) { float2 a = __ldg(&x2[j1.x * F_VEC2 + lane]);
                            acc.x += a.x; acc.y += a.y; }
        if (base + 5 < c) { float2 a = __ldg(&x2[j1.y * F_VEC2 + lane]);
                            acc.x += a.x; acc.y += a.y; }
        if (base + 6 < c) { float2 a = __ldg(&x2[j1.z * F_VEC2 + lane]);
                            acc.x += a.x; acc.y += a.y; }
        if (base + 7 < c) { float2 a = __ldg(&x2[j1.w * F_VEC2 + lane]);
                            acc.x += a.x; acc.y += a.y; }
    }

    float w = 1.0f / (float)(c > 0 ? c : 1);
    acc.x *= w; acc.y *= w;
    out2[node * F_VEC2 + lane] = acc;

    // restore cursor to 0 for the next launch (replaces the memset pass)
    if (lane == 0) cursor[node] = 0;
}

// ---------------------------------------------------------------------------
// Launch
// ---------------------------------------------------------------------------
extern "C" void kernel_launch(void* const* d_in, const int* in_sizes, int n_in,
                              void* d_out, int out_size) {
    const float* x   = (const float*)d_in[0];
    const int*   src = (const int*)d_in[1];
    const int*   tgt = (const int*)d_in[2];
    float*       out = (float*)d_out;

    int n_nodes  = in_sizes[0] / F_DIM;   // 100000
    int n_edges  = in_sizes[1];           // 800000
    int n_groups = n_edges / 4;

    int *cursor, *bucket;
    cudaGetSymbolAddress((void**)&cursor, g_cursor);
    cudaGetSymbolAddress((void**)&bucket, g_bucket);

    const int B = 256;

    // no memset: cursor is zero on first launch (static init) and k_seg
    // returns it to zero at the end of every launch.
    k_sortsrc<<<(n_groups + B - 1) / B, B>>>((const int4*)src, (const int4*)tgt,
                                             cursor, bucket, n_groups);
    {
        // one warp per node
        long long threads = (long long)n_nodes * 32;
        int grid = (int)((threads + B - 1) / B);
        k_seg<<<grid, B>>>((const float2*)x, bucket, cursor,
                           (float2*)out, n_nodes);
    }
}